// round 4
// baseline (speedup 1.0000x reference)
#include <cuda_runtime.h>
#include <cuda_bf16.h>

// Inputs (metadata order):
//   0: shape    float32 [B, C, H, W]       B=16, C=128, H=W=128
//   1: size     int32   scalar (S=1024)    (derived from sizes instead)
//   2: saliency float32 [B, 1, H, W]       (unused by reference math)
//   3: mask     int32   [B, K]             K=256
//   4: ind      int32   [B, K]             values in [0, H*W)
//   5: target   float32 [B, K, S]
// Output: float32 [1]  = sum(|pred*m - target*m|) / (sum(m)*S + 1e-4)

__device__ float g_loss_acc;
__device__ int   g_mask_cnt;

__global__ void ml_zero_kernel() {
    g_loss_acc = 0.0f;
    g_mask_cnt = 0;
}

__global__ void __launch_bounds__(128) ml_main_kernel(
    const float* __restrict__ shape,   // [B, C, HW]
    const int*   __restrict__ mask,    // [B*K]
    const int*   __restrict__ ind,     // [B*K]
    const float* __restrict__ target,  // [B*K, S]
    int C, int HW, int K, int S)
{
    const int bk = blockIdx.x;          // b*K + k
    if (mask[bk] == 0) return;          // masked-out pair: contributes nothing

    const int t = threadIdx.x;
    const int b = bk / K;
    const int hw = ind[bk];

    extern __shared__ float pred[];     // [C]
    // Cooperative gather of the per-object channel vector (strided by HW)
    for (int c = t; c < C; c += blockDim.x) {
        pred[c] = shape[(size_t)b * C * HW + (size_t)c * HW + hw];
    }
    __syncthreads();

    const float scale = (float)C / (float)S;
    const float cmax  = (float)(C - 1);
    const float* __restrict__ tg = target + (size_t)bk * S;

    float acc = 0.0f;
    // Coalesced over threads: s = t, t+128, ... each iter reads 512B contiguous
    for (int s = t; s < S; s += blockDim.x) {
        float pos = ((float)s + 0.5f) * scale - 0.5f;
        pos = fminf(fmaxf(pos, 0.0f), cmax);
        int lo = (int)pos;                 // pos >= 0, trunc == floor
        int hi = min(lo + 1, C - 1);
        float w = pos - (float)lo;
        float v = pred[lo] * (1.0f - w) + pred[hi] * w;  // match reference form
        acc += fabsf(v - tg[s]);
    }

    // Block reduction: warp shuffle then cross-warp via shared
    #pragma unroll
    for (int off = 16; off > 0; off >>= 1)
        acc += __shfl_down_sync(0xFFFFFFFFu, acc, off);

    __shared__ float warp_sums[4];
    const int lane = t & 31;
    const int wid  = t >> 5;
    if (lane == 0) warp_sums[wid] = acc;
    __syncthreads();

    if (t == 0) {
        float s0 = warp_sums[0] + warp_sums[1] + warp_sums[2] + warp_sums[3];
        atomicAdd(&g_loss_acc, s0);
        atomicAdd(&g_mask_cnt, 1);
    }
}

__global__ void ml_finalize_kernel(float* __restrict__ out, int S) {
    out[0] = g_loss_acc / ((float)g_mask_cnt * (float)S + 1e-4f);
}

extern "C" void kernel_launch(void* const* d_in, const int* in_sizes, int n_in,
                              void* d_out, int out_size)
{
    const float* shape  = (const float*)d_in[0];
    const int*   mask   = (const int*)  d_in[3];
    const int*   ind    = (const int*)  d_in[4];
    const float* target = (const float*)d_in[5];
    float* out = (float*)d_out;

    // Shape derivation (B is not derivable from element counts; fixed per problem)
    const int B   = 16;
    const int C   = in_sizes[0] / in_sizes[2];   // shape / saliency = C
    const int HW  = in_sizes[2] / B;             // saliency = B*HW
    const int K   = in_sizes[3] / B;             // mask = B*K
    const int S   = in_sizes[5] / in_sizes[3];   // target / mask = S

    const int nPairs = B * K;
    const int threads = 128;
    const size_t smem = (size_t)C * sizeof(float);

    ml_zero_kernel<<<1, 1>>>();
    ml_main_kernel<<<nPairs, threads, smem>>>(shape, mask, ind, target, C, HW, K, S);
    ml_finalize_kernel<<<1, 1>>>(out, S);
}

// round 6
// speedup vs baseline: 1.3591x; 1.3591x over previous
#include <cuda_runtime.h>
#include <cuda_bf16.h>

// Inputs (metadata order):
//   0: shape    float32 [B, C, H, W]       B=16, C=128, H=W=128
//   1: size     int32   scalar (S=1024)
//   2: saliency float32 [B, 1, H, W]       (unused by reference math)
//   3: mask     int32   [B, K]             K=256
//   4: ind      int32   [B, K]
//   5: target   float32 [B, K, S]
// Output: float32 [1]  = sum(|pred*m - target*m|) / (sum(m)*S + 1e-4)
//
// Single fused kernel: per-(b,k) block computes its partial L1, atomically
// accumulates into __device__ globals; the LAST block to finish (tracked via
// an arrival counter) finalizes d_out and resets the globals so every graph
// replay is deterministic.

__device__ float        g_loss_acc;   // zero-initialized; reset by last block
__device__ int          g_mask_cnt;
__device__ unsigned int g_done;

__global__ void __launch_bounds__(128) ml_fused_kernel(
    const float* __restrict__ shape,   // [B, C, HW]
    const int*   __restrict__ mask,    // [B*K]
    const int*   __restrict__ ind,     // [B*K]
    const float* __restrict__ target,  // [B*K, S]
    float*       __restrict__ out,
    int C, int HW, int K, int S, int nBlocks)
{
    const int bk = blockIdx.x;          // b*K + k
    const int t  = threadIdx.x;
    const int active = mask[bk];

    __shared__ float warp_sums[4];
    extern __shared__ float pred[];     // [C]

    if (active) {
        const int b  = bk / K;
        const int hw = ind[bk];

        // Cooperative gather of the per-object channel vector (strided by HW)
        for (int c = t; c < C; c += blockDim.x) {
            pred[c] = __ldg(&shape[(size_t)b * C * HW + (size_t)c * HW + hw]);
        }
        __syncthreads();

        const float scale = (float)C / (float)S;
        const float cmax  = (float)(C - 1);
        const float* __restrict__ tg = target + (size_t)bk * S;

        float acc = 0.0f;
        if ((S & 3) == 0) {
            // Vectorized: thread t handles quads s4 = t, t+128, ...
            const float4* __restrict__ tg4 = (const float4*)tg;
            const int nQuads = S >> 2;
            for (int q = t; q < nQuads; q += blockDim.x) {
                const float4 tv = __ldg(&tg4[q]);
                const int s0 = q << 2;
                #pragma unroll
                for (int j = 0; j < 4; j++) {
                    float pos = ((float)(s0 + j) + 0.5f) * scale - 0.5f;
                    pos = fminf(fmaxf(pos, 0.0f), cmax);
                    int lo = (int)pos;
                    int hi = min(lo + 1, C - 1);
                    float w = pos - (float)lo;
                    float v = pred[lo] * (1.0f - w) + pred[hi] * w;
                    float tj = (j == 0) ? tv.x : (j == 1) ? tv.y : (j == 2) ? tv.z : tv.w;
                    acc += fabsf(v - tj);
                }
            }
        } else {
            for (int s = t; s < S; s += blockDim.x) {
                float pos = ((float)s + 0.5f) * scale - 0.5f;
                pos = fminf(fmaxf(pos, 0.0f), cmax);
                int lo = (int)pos;
                int hi = min(lo + 1, C - 1);
                float w = pos - (float)lo;
                float v = pred[lo] * (1.0f - w) + pred[hi] * w;
                acc += fabsf(v - tg[s]);
            }
        }

        // Block reduction
        #pragma unroll
        for (int off = 16; off > 0; off >>= 1)
            acc += __shfl_down_sync(0xFFFFFFFFu, acc, off);

        const int lane = t & 31;
        const int wid  = t >> 5;
        if (lane == 0) warp_sums[wid] = acc;
        __syncthreads();

        if (t == 0) {
            float s0 = warp_sums[0] + warp_sums[1] + warp_sums[2] + warp_sums[3];
            atomicAdd(&g_loss_acc, s0);
            atomicAdd(&g_mask_cnt, 1);
        }
    }

    // Completion protocol: every block (active or not) arrives exactly once.
    if (t == 0) {
        __threadfence();  // make this block's atomics globally visible
        unsigned int ticket = atomicAdd(&g_done, 1u);
        if (ticket == (unsigned int)(nBlocks - 1)) {
            // All other blocks' atomics are visible (they fenced before arriving).
            float total = atomicAdd(&g_loss_acc, 0.0f);
            int   cnt   = atomicAdd(&g_mask_cnt, 0);
            out[0] = total / ((float)cnt * (float)S + 1e-4f);
            // Reset state for the next graph replay (deterministic).
            g_loss_acc = 0.0f;
            g_mask_cnt = 0;
            __threadfence();
            g_done = 0u;
        }
    }
}

extern "C" void kernel_launch(void* const* d_in, const int* in_sizes, int n_in,
                              void* d_out, int out_size)
{
    const float* shape  = (const float*)d_in[0];
    const int*   mask   = (const int*)  d_in[3];
    const int*   ind    = (const int*)  d_in[4];
    const float* target = (const float*)d_in[5];
    float* out = (float*)d_out;

    const int B   = 16;
    const int C   = in_sizes[0] / in_sizes[2];   // shape / saliency = C
    const int HW  = in_sizes[2] / B;             // saliency = B*HW
    const int K   = in_sizes[3] / B;             // mask = B*K
    const int S   = in_sizes[5] / in_sizes[3];   // target / mask = S

    const int nPairs  = B * K;
    const int threads = 128;
    const size_t smem = (size_t)C * sizeof(float);

    ml_fused_kernel<<<nPairs, threads, smem>>>(shape, mask, ind, target, out,
                                               C, HW, K, S, nPairs);
}

// round 8
// speedup vs baseline: 1.3868x; 1.0204x over previous
#include <cuda_runtime.h>
#include <cuda_bf16.h>

// Inputs (metadata order):
//   0: shape    float32 [B, C, H, W]       B=16, C=128, H=W=128
//   1: size     int32   scalar (S=1024)
//   2: saliency float32 [B, 1, H, W]       (unused by reference math)
//   3: mask     int32   [B, K]             K=256
//   4: ind      int32   [B, K]
//   5: target   float32 [B, K, S]
// Output: float32 [1]  = sum(|pred*m - target*m|) / (sum(m)*S + 1e-4)
//
// Single fused kernel, last-block finalize. Key optimization this round:
// target float4 loads and the scattered gather load are issued TOGETHER
// (before __syncthreads), so the two DRAM latency streams overlap instead
// of serializing.

__device__ float        g_loss_acc;   // zero-init; reset by last block
__device__ int          g_mask_cnt;
__device__ unsigned int g_done;

__device__ __forceinline__ float interp_abs(const float* __restrict__ pred,
                                            int s, float scale, float cmax,
                                            int C, float tj)
{
    float pos = ((float)s + 0.5f) * scale - 0.5f;
    pos = fminf(fmaxf(pos, 0.0f), cmax);
    int lo = (int)pos;                 // pos >= 0 -> trunc == floor
    int hi = min(lo + 1, C - 1);
    float w = pos - (float)lo;
    float v = pred[lo] * (1.0f - w) + pred[hi] * w;
    return fabsf(v - tj);
}

__global__ void __launch_bounds__(128) ml_fused_kernel(
    const float* __restrict__ shape,   // [B, C, HW]
    const int*   __restrict__ mask,    // [B*K]
    const int*   __restrict__ ind,     // [B*K]
    const float* __restrict__ target,  // [B*K, S]
    float*       __restrict__ out,
    int C, int HW, int K, int S, int nBlocks)
{
    const int bk = blockIdx.x;          // b*K + k
    const int t  = threadIdx.x;
    const int active = mask[bk];

    __shared__ float warp_sums[4];
    extern __shared__ float pred[];     // [C]

    if (active) {
        const int b  = bk / K;
        const int hw = ind[bk];

        const float scale = (float)C / (float)S;
        const float cmax  = (float)(C - 1);
        const float* __restrict__ tg  = target + (size_t)bk * S;
        const float4* __restrict__ tg4 = (const float4*)tg;

        float acc = 0.0f;

        if (C == (int)blockDim.x && S == (int)blockDim.x * 8) {
            // ---- specialized fast path: C==128, S==1024, 128 threads ----
            // Issue ALL global loads up front: 2 target quads + 1 gather.
            // Independent -> 3 outstanding DRAM requests per thread, the
            // gather latency hides under the target latency.
            const float4 tv0 = __ldg(&tg4[t]);
            const float4 tv1 = __ldg(&tg4[t + 128]);
            const float  pv  = __ldg(&shape[(size_t)b * C * HW + (size_t)t * HW + hw]);
            pred[t] = pv;
            __syncthreads();

            const int s0 = t << 2;            // quad 0: s = 4t .. 4t+3
            const int s1 = (t + 128) << 2;    // quad 1
            acc += interp_abs(pred, s0 + 0, scale, cmax, C, tv0.x);
            acc += interp_abs(pred, s0 + 1, scale, cmax, C, tv0.y);
            acc += interp_abs(pred, s0 + 2, scale, cmax, C, tv0.z);
            acc += interp_abs(pred, s0 + 3, scale, cmax, C, tv0.w);
            acc += interp_abs(pred, s1 + 0, scale, cmax, C, tv1.x);
            acc += interp_abs(pred, s1 + 1, scale, cmax, C, tv1.y);
            acc += interp_abs(pred, s1 + 2, scale, cmax, C, tv1.z);
            acc += interp_abs(pred, s1 + 3, scale, cmax, C, tv1.w);
        } else {
            // ---- generic fallback ----
            for (int c = t; c < C; c += blockDim.x)
                pred[c] = __ldg(&shape[(size_t)b * C * HW + (size_t)c * HW + hw]);
            __syncthreads();

            if ((S & 3) == 0) {
                const int nQuads = S >> 2;
                for (int q = t; q < nQuads; q += blockDim.x) {
                    const float4 tv = __ldg(&tg4[q]);
                    const int s0 = q << 2;
                    acc += interp_abs(pred, s0 + 0, scale, cmax, C, tv.x);
                    acc += interp_abs(pred, s0 + 1, scale, cmax, C, tv.y);
                    acc += interp_abs(pred, s0 + 2, scale, cmax, C, tv.z);
                    acc += interp_abs(pred, s0 + 3, scale, cmax, C, tv.w);
                }
            } else {
                for (int s = t; s < S; s += blockDim.x)
                    acc += interp_abs(pred, s, scale, cmax, C, __ldg(&tg[s]));
            }
        }

        // Block reduction
        #pragma unroll
        for (int off = 16; off > 0; off >>= 1)
            acc += __shfl_down_sync(0xFFFFFFFFu, acc, off);

        const int lane = t & 31;
        const int wid  = t >> 5;
        if (lane == 0) warp_sums[wid] = acc;
        __syncthreads();

        if (t == 0) {
            float s0 = warp_sums[0] + warp_sums[1] + warp_sums[2] + warp_sums[3];
            atomicAdd(&g_loss_acc, s0);
            atomicAdd(&g_mask_cnt, 1);
        }
    }

    // Completion protocol: every block arrives exactly once.
    if (t == 0) {
        __threadfence();
        unsigned int ticket = atomicAdd(&g_done, 1u);
        if (ticket == (unsigned int)(nBlocks - 1)) {
            float total = atomicAdd(&g_loss_acc, 0.0f);
            int   cnt   = atomicAdd(&g_mask_cnt, 0);
            out[0] = total / ((float)cnt * (float)S + 1e-4f);
            g_loss_acc = 0.0f;
            g_mask_cnt = 0;
            __threadfence();
            g_done = 0u;
        }
    }
}

extern "C" void kernel_launch(void* const* d_in, const int* in_sizes, int n_in,
                              void* d_out, int out_size)
{
    const float* shape  = (const float*)d_in[0];
    const int*   mask   = (const int*)  d_in[3];
    const int*   ind    = (const int*)  d_in[4];
    const float* target = (const float*)d_in[5];
    float* out = (float*)d_out;

    const int B   = 16;
    const int C   = in_sizes[0] / in_sizes[2];   // shape / saliency = C
    const int HW  = in_sizes[2] / B;             // saliency = B*HW
    const int K   = in_sizes[3] / B;             // mask = B*K
    const int S   = in_sizes[5] / in_sizes[3];   // target / mask = S

    const int nPairs  = B * K;
    const int threads = 128;
    const size_t smem = (size_t)C * sizeof(float);

    ml_fused_kernel<<<nPairs, threads, smem>>>(shape, mask, ind, target, out,
                                               C, HW, K, S, nPairs);
}

// round 10
// speedup vs baseline: 1.6172x; 1.1662x over previous
#include <cuda_runtime.h>
#include <cuda_bf16.h>

// Inputs (metadata order):
//   0: shape    float32 [B, C, H, W]       B=16, C=128, H=W=128
//   1: size     int32   scalar (S=1024)
//   2: saliency float32 [B, 1, H, W]       (unused)
//   3: mask     int32   [B, K]             K=256
//   4: ind      int32   [B, K]
//   5: target   float32 [B, K, S]
// Output: float32 [1] = sum(|pred*m - target*m|) / (sum(m)*S + 1e-4)
//
// Specialized path: 256-thread blocks, each handling 4 (b,k) pairs.
// ALL global loads (4 target quads + 2 gathers per thread) are issued before
// the single __syncthreads so ~6 DRAM requests per thread are in flight.
// Interp coefficients are computed once per thread and reused for all 4 pairs.

__device__ float        g_loss_acc;   // zero-init; reset by last block
__device__ int          g_mask_cnt;
__device__ unsigned int g_done;

__device__ __forceinline__ void finalize_and_reset(float* __restrict__ out,
                                                   int S, int nBlocks)
{
    __threadfence();
    unsigned int ticket = atomicAdd(&g_done, 1u);
    if (ticket == (unsigned int)(nBlocks - 1)) {
        float total = atomicAdd(&g_loss_acc, 0.0f);
        int   cnt   = atomicAdd(&g_mask_cnt, 0);
        out[0] = total / ((float)cnt * (float)S + 1e-4f);
        g_loss_acc = 0.0f;
        g_mask_cnt = 0;
        __threadfence();
        g_done = 0u;
    }
}

// ---------------- specialized: C=128, S=1024, P=4 pairs/block ----------------
__global__ void __launch_bounds__(256) ml_fused4_kernel(
    const float* __restrict__ shape,   // [B, C, HW]
    const int*   __restrict__ mask,    // [B*K]
    const int*   __restrict__ ind,     // [B*K]
    const float* __restrict__ target,  // [B*K, S]
    float*       __restrict__ out,
    int HW, int K, int nBlocks)
{
    constexpr int C = 128, S = 1024, P = 4;
    const int base = blockIdx.x * P;    // first pair of this block
    const int t    = threadIdx.x;       // 0..255

    __shared__ float pred[P][C];
    __shared__ float warp_sums[8];

    // Per-pair metadata (small, L1/L2-broadcast)
    int   m[P];
    #pragma unroll
    for (int p = 0; p < P; p++) m[p] = mask[base + p];

    // ---- issue ALL global loads up front ----
    // Target: thread t owns quad q=t of every pair (s = 4t..4t+3).
    float4 tv[P];
    #pragma unroll
    for (int p = 0; p < P; p++) {
        if (m[p]) {
            const float4* tg4 = (const float4*)(target + (size_t)(base + p) * S);
            tv[p] = __ldg(&tg4[t]);
        }
    }
    // Gather: thread t loads channel (t&127) of pairs (t>>7) and (t>>7)+2.
    {
        const int cA = t & 127;
        const int pA = t >> 7;          // 0 or 1
        #pragma unroll
        for (int j = 0; j < 2; j++) {
            const int p = pA + 2 * j;
            if (m[p]) {
                const int bkp = base + p;
                const int b   = bkp / K;
                const int hw  = ind[bkp];
                pred[p][cA] = __ldg(&shape[(size_t)b * C * HW + (size_t)cA * HW + hw]);
            }
        }
    }
    __syncthreads();

    // ---- interp coefficients: depend only on s, shared across pairs ----
    const float scale = (float)C / (float)S;
    const float cmax  = (float)(C - 1);
    int   lo[4], hi[4];
    float w[4];
    #pragma unroll
    for (int j = 0; j < 4; j++) {
        float pos = ((float)(4 * t + j) + 0.5f) * scale - 0.5f;
        pos = fminf(fmaxf(pos, 0.0f), cmax);
        lo[j] = (int)pos;
        hi[j] = min(lo[j] + 1, C - 1);
        w[j]  = pos - (float)lo[j];
    }

    float acc = 0.0f;
    #pragma unroll
    for (int p = 0; p < P; p++) {
        if (m[p]) {
            const float* pr = pred[p];
            float t0 = tv[p].x, t1 = tv[p].y, t2 = tv[p].z, t3 = tv[p].w;
            acc += fabsf(pr[lo[0]] * (1.0f - w[0]) + pr[hi[0]] * w[0] - t0);
            acc += fabsf(pr[lo[1]] * (1.0f - w[1]) + pr[hi[1]] * w[1] - t1);
            acc += fabsf(pr[lo[2]] * (1.0f - w[2]) + pr[hi[2]] * w[2] - t2);
            acc += fabsf(pr[lo[3]] * (1.0f - w[3]) + pr[hi[3]] * w[3] - t3);
        }
    }

    // ---- block reduction over 8 warps ----
    #pragma unroll
    for (int off = 16; off > 0; off >>= 1)
        acc += __shfl_down_sync(0xFFFFFFFFu, acc, off);
    const int lane = t & 31;
    const int wid  = t >> 5;
    if (lane == 0) warp_sums[wid] = acc;
    __syncthreads();

    if (t == 0) {
        float s0 = 0.0f;
        #pragma unroll
        for (int i = 0; i < 8; i++) s0 += warp_sums[i];
        int cnt = m[0] + m[1] + m[2] + m[3];
        if (s0 != 0.0f || cnt) {
            atomicAdd(&g_loss_acc, s0);
            atomicAdd(&g_mask_cnt, cnt);
        }
        finalize_and_reset(out, S, nBlocks);
    }
}

// ---------------- generic fallback: one pair per 128-thread block ------------
__global__ void __launch_bounds__(128) ml_fused_kernel(
    const float* __restrict__ shape,
    const int*   __restrict__ mask,
    const int*   __restrict__ ind,
    const float* __restrict__ target,
    float*       __restrict__ out,
    int C, int HW, int K, int S, int nBlocks)
{
    const int bk = blockIdx.x;
    const int t  = threadIdx.x;
    const int active = mask[bk];

    __shared__ float warp_sums[4];
    extern __shared__ float pred[];

    float blocksum = 0.0f;
    if (active) {
        const int b  = bk / K;
        const int hw = ind[bk];
        for (int c = t; c < C; c += blockDim.x)
            pred[c] = __ldg(&shape[(size_t)b * C * HW + (size_t)c * HW + hw]);
        __syncthreads();

        const float scale = (float)C / (float)S;
        const float cmax  = (float)(C - 1);
        const float* tg = target + (size_t)bk * S;

        float acc = 0.0f;
        for (int s = t; s < S; s += blockDim.x) {
            float pos = ((float)s + 0.5f) * scale - 0.5f;
            pos = fminf(fmaxf(pos, 0.0f), cmax);
            int lo = (int)pos;
            int hi = min(lo + 1, C - 1);
            float w = pos - (float)lo;
            acc += fabsf(pred[lo] * (1.0f - w) + pred[hi] * w - __ldg(&tg[s]));
        }
        #pragma unroll
        for (int off = 16; off > 0; off >>= 1)
            acc += __shfl_down_sync(0xFFFFFFFFu, acc, off);
        const int lane = t & 31, wid = t >> 5;
        if (lane == 0) warp_sums[wid] = acc;
        __syncthreads();
        if (t == 0)
            blocksum = warp_sums[0] + warp_sums[1] + warp_sums[2] + warp_sums[3];
    }

    if (t == 0) {
        if (active) {
            atomicAdd(&g_loss_acc, blocksum);
            atomicAdd(&g_mask_cnt, 1);
        }
        finalize_and_reset(out, S, nBlocks);
    }
}

extern "C" void kernel_launch(void* const* d_in, const int* in_sizes, int n_in,
                              void* d_out, int out_size)
{
    const float* shape  = (const float*)d_in[0];
    const int*   mask   = (const int*)  d_in[3];
    const int*   ind    = (const int*)  d_in[4];
    const float* target = (const float*)d_in[5];
    float* out = (float*)d_out;

    const int B   = 16;
    const int C   = in_sizes[0] / in_sizes[2];   // shape / saliency = C
    const int HW  = in_sizes[2] / B;             // saliency = B*HW
    const int K   = in_sizes[3] / B;             // mask = B*K
    const int S   = in_sizes[5] / in_sizes[3];   // target / mask = S

    const int nPairs = B * K;

    if (C == 128 && S == 1024 && (nPairs % 4) == 0) {
        const int nBlocks = nPairs / 4;
        ml_fused4_kernel<<<nBlocks, 256>>>(shape, mask, ind, target, out,
                                           HW, K, nBlocks);
    } else {
        const size_t smem = (size_t)C * sizeof(float);
        ml_fused_kernel<<<nPairs, 128, smem>>>(shape, mask, ind, target, out,
                                               C, HW, K, S, nPairs);
    }
}